// round 4
// baseline (speedup 1.0000x reference)
#include <cuda_runtime.h>
#include <cstdint>

// Problem constants
#define T_TOK 4096
#define DIM   1024
#define HID   5632
#define EACT  4
#define TB    1024   // token tile for scratch reuse

// Scratch (no cudaMalloc allowed): combine weights + intermediate G (tf32 bits)
// G covers one token-block only: 1024 x 5632 x 4B = 23 MB.
__device__ float    g_cw[T_TOK * EACT];
__device__ uint32_t g_G[(size_t)TB * HID];

__device__ __forceinline__ uint32_t f2tf32(float f) {
    uint32_t r;
    asm("cvt.rna.tf32.f32 %0, %1;" : "=r"(r) : "f"(f));
    return r;
}

__device__ __forceinline__ void mma8(float* c,
                                     uint32_t a0, uint32_t a1, uint32_t a2, uint32_t a3,
                                     uint32_t b0, uint32_t b1) {
    asm volatile(
        "mma.sync.aligned.m16n8k8.row.col.f32.tf32.tf32.f32 "
        "{%0,%1,%2,%3}, {%4,%5,%6,%7}, {%8,%9}, {%0,%1,%2,%3};\n"
        : "+f"(c[0]), "+f"(c[1]), "+f"(c[2]), "+f"(c[3])
        : "r"(a0), "r"(a1), "r"(a2), "r"(a3), "r"(b0), "r"(b1));
}

__device__ __forceinline__ float silu_f(float v) {
    return v / (1.0f + __expf(-v));
}

// ---------------------------------------------------------------------------
// Gate: one warp per token. logits over experts 0..3 (4..7 masked to -inf),
// softmax -> top-2 -> renormalize == softmax over the top-2 logits.
// ---------------------------------------------------------------------------
__global__ void gate_kernel(const float* __restrict__ x,
                            const float* __restrict__ gw) {
    int warp = (blockIdx.x * blockDim.x + threadIdx.x) >> 5;
    int lane = threadIdx.x & 31;
    if (warp >= T_TOK) return;

    const float* xr = x + (size_t)warp * DIM;
    float p0 = 0.f, p1 = 0.f, p2 = 0.f, p3 = 0.f;
    for (int d = lane; d < DIM; d += 32) {
        float xv = xr[d];
        p0 += xv * gw[0 * DIM + d];
        p1 += xv * gw[1 * DIM + d];
        p2 += xv * gw[2 * DIM + d];
        p3 += xv * gw[3 * DIM + d];
    }
    #pragma unroll
    for (int off = 16; off; off >>= 1) {
        p0 += __shfl_down_sync(0xffffffff, p0, off);
        p1 += __shfl_down_sync(0xffffffff, p1, off);
        p2 += __shfl_down_sync(0xffffffff, p2, off);
        p3 += __shfl_down_sync(0xffffffff, p3, off);
    }
    if (lane == 0) {
        float l[4] = {p0, p1, p2, p3};
        int i0 = 0;
        #pragma unroll
        for (int e = 1; e < 4; e++) if (l[e] > l[i0]) i0 = e;
        int i1 = -1;
        #pragma unroll
        for (int e = 0; e < 4; e++) {
            if (e == i0) continue;
            if (i1 < 0 || l[e] > l[i1]) i1 = e;
        }
        // normalized top-2 weights: softmax over {l[i0], l[i1]}
        float w0 = 1.0f / (1.0f + __expf(l[i1] - l[i0]));
        float w1 = 1.0f - w0;
        float* cwr = g_cw + warp * 4;
        cwr[0] = 0.f; cwr[1] = 0.f; cwr[2] = 0.f; cwr[3] = 0.f;
        cwr[i0] = w0;
        cwr[i1] = w1;
    }
}

// ---------------------------------------------------------------------------
// GEMM13: G[t,h] = tf32( cw[t,e] * silu(X@W1)[t,h] * (X@W3)[t,h] )
// X rows offset by tok0; G holds TB rows.
// Tile: BM=128, BN=64, BK=32; 256 threads (8 warps, 4x2), warp tile 32x32.
// ---------------------------------------------------------------------------
__global__ void __launch_bounds__(256) gemm13_kernel(
    const float* __restrict__ X,
    const float* __restrict__ W1,
    const float* __restrict__ W3,
    int eidx, int tok0)
{
    __shared__ uint32_t As[128][33];
    __shared__ uint32_t B1s[32][65];
    __shared__ uint32_t B3s[32][65];

    const int tid  = threadIdx.x;
    const int bm   = blockIdx.y * 128;           // row within token block
    const int bn   = blockIdx.x * 64;
    const int warp = tid >> 5;
    const int lane = tid & 31;
    const int wm   = (warp & 3) * 32;
    const int wn   = (warp >> 2) * 32;
    const int g    = lane >> 2;
    const int tig  = lane & 3;

    float accA[2][4][4];
    float accB[2][4][4];
    #pragma unroll
    for (int mt = 0; mt < 2; mt++)
        #pragma unroll
        for (int nt = 0; nt < 4; nt++)
            #pragma unroll
            for (int i = 0; i < 4; i++) { accA[mt][nt][i] = 0.f; accB[mt][nt][i] = 0.f; }

    for (int k0 = 0; k0 < DIM; k0 += 32) {
        #pragma unroll
        for (int i = 0; i < 4; i++) {
            int idx = tid + i * 256;
            int row = idx >> 3;
            int c4  = (idx & 7) * 4;
            float4 v = *(const float4*)(X + (size_t)(tok0 + bm + row) * DIM + k0 + c4);
            As[row][c4 + 0] = f2tf32(v.x);
            As[row][c4 + 1] = f2tf32(v.y);
            As[row][c4 + 2] = f2tf32(v.z);
            As[row][c4 + 3] = f2tf32(v.w);
        }
        #pragma unroll
        for (int i = 0; i < 2; i++) {
            int idx = tid + i * 256;
            int row = idx >> 4;
            int c4  = (idx & 15) * 4;
            size_t goff = (size_t)(k0 + row) * HID + bn + c4;
            float4 v1 = *(const float4*)(W1 + goff);
            B1s[row][c4 + 0] = f2tf32(v1.x);
            B1s[row][c4 + 1] = f2tf32(v1.y);
            B1s[row][c4 + 2] = f2tf32(v1.z);
            B1s[row][c4 + 3] = f2tf32(v1.w);
            float4 v3 = *(const float4*)(W3 + goff);
            B3s[row][c4 + 0] = f2tf32(v3.x);
            B3s[row][c4 + 1] = f2tf32(v3.y);
            B3s[row][c4 + 2] = f2tf32(v3.z);
            B3s[row][c4 + 3] = f2tf32(v3.w);
        }
        __syncthreads();

        #pragma unroll
        for (int kk = 0; kk < 32; kk += 8) {
            uint32_t a[2][4];
            #pragma unroll
            for (int mt = 0; mt < 2; mt++) {
                int r = wm + mt * 16 + g;
                a[mt][0] = As[r][kk + tig];
                a[mt][1] = As[r + 8][kk + tig];
                a[mt][2] = As[r][kk + tig + 4];
                a[mt][3] = As[r + 8][kk + tig + 4];
            }
            #pragma unroll
            for (int nt = 0; nt < 4; nt++) {
                int c = wn + nt * 8 + g;
                uint32_t b1a = B1s[kk + tig][c];
                uint32_t b1b = B1s[kk + tig + 4][c];
                uint32_t b3a = B3s[kk + tig][c];
                uint32_t b3b = B3s[kk + tig + 4][c];
                #pragma unroll
                for (int mt = 0; mt < 2; mt++) {
                    mma8(accA[mt][nt], a[mt][0], a[mt][1], a[mt][2], a[mt][3], b1a, b1b);
                    mma8(accB[mt][nt], a[mt][0], a[mt][1], a[mt][2], a[mt][3], b3a, b3b);
                }
            }
        }
        __syncthreads();
    }

    // ---- epilogue: G = tf32(cw * silu(A) * B) ----
    #pragma unroll
    for (int mt = 0; mt < 2; mt++) {
        int r0 = bm + wm + mt * 16 + g;       // row within token block
        int r1 = r0 + 8;
        float cw0 = g_cw[(tok0 + r0) * 4 + eidx];
        float cw1 = g_cw[(tok0 + r1) * 4 + eidx];
        #pragma unroll
        for (int nt = 0; nt < 4; nt++) {
            int c = bn + wn + nt * 8 + 2 * tig;
            float v00 = silu_f(accA[mt][nt][0]) * accB[mt][nt][0] * cw0;
            float v01 = silu_f(accA[mt][nt][1]) * accB[mt][nt][1] * cw0;
            float v10 = silu_f(accA[mt][nt][2]) * accB[mt][nt][2] * cw1;
            float v11 = silu_f(accA[mt][nt][3]) * accB[mt][nt][3] * cw1;
            uint2 s0 = make_uint2(f2tf32(v00), f2tf32(v01));
            uint2 s1 = make_uint2(f2tf32(v10), f2tf32(v11));
            *(uint2*)&g_G[(size_t)r0 * HID + c] = s0;
            *(uint2*)&g_G[(size_t)r1 * HID + c] = s1;
        }
    }
}

// ---------------------------------------------------------------------------
// GEMM2: out[tok0+t,d] (+)= (G @ W2)[t,d]
// G: [TB,5632] tf32 bits ; W2: [5632,1024] row-major f32
// ---------------------------------------------------------------------------
__global__ void __launch_bounds__(256) gemm2_kernel(
    const float* __restrict__ W2,
    float* __restrict__ out,
    int first, int tok0)
{
    __shared__ uint32_t As[128][33];
    __shared__ uint32_t Bs[32][65];

    const int tid  = threadIdx.x;
    const int bm   = blockIdx.y * 128;
    const int bn   = blockIdx.x * 64;
    const int warp = tid >> 5;
    const int lane = tid & 31;
    const int wm   = (warp & 3) * 32;
    const int wn   = (warp >> 2) * 32;
    const int g    = lane >> 2;
    const int tig  = lane & 3;

    float acc[2][4][4];
    #pragma unroll
    for (int mt = 0; mt < 2; mt++)
        #pragma unroll
        for (int nt = 0; nt < 4; nt++)
            #pragma unroll
            for (int i = 0; i < 4; i++) acc[mt][nt][i] = 0.f;

    for (int k0 = 0; k0 < HID; k0 += 32) {
        #pragma unroll
        for (int i = 0; i < 4; i++) {
            int idx = tid + i * 256;
            int row = idx >> 3;
            int c4  = (idx & 7) * 4;
            uint4 v = *(const uint4*)&g_G[(size_t)(bm + row) * HID + k0 + c4];
            As[row][c4 + 0] = v.x;
            As[row][c4 + 1] = v.y;
            As[row][c4 + 2] = v.z;
            As[row][c4 + 3] = v.w;
        }
        #pragma unroll
        for (int i = 0; i < 2; i++) {
            int idx = tid + i * 256;
            int row = idx >> 4;
            int c4  = (idx & 15) * 4;
            float4 v = *(const float4*)(W2 + (size_t)(k0 + row) * DIM + bn + c4);
            Bs[row][c4 + 0] = f2tf32(v.x);
            Bs[row][c4 + 1] = f2tf32(v.y);
            Bs[row][c4 + 2] = f2tf32(v.z);
            Bs[row][c4 + 3] = f2tf32(v.w);
        }
        __syncthreads();

        #pragma unroll
        for (int kk = 0; kk < 32; kk += 8) {
            uint32_t a[2][4];
            #pragma unroll
            for (int mt = 0; mt < 2; mt++) {
                int r = wm + mt * 16 + g;
                a[mt][0] = As[r][kk + tig];
                a[mt][1] = As[r + 8][kk + tig];
                a[mt][2] = As[r][kk + tig + 4];
                a[mt][3] = As[r + 8][kk + tig + 4];
            }
            #pragma unroll
            for (int nt = 0; nt < 4; nt++) {
                int c = wn + nt * 8 + g;
                uint32_t b0 = Bs[kk + tig][c];
                uint32_t b1 = Bs[kk + tig + 4][c];
                #pragma unroll
                for (int mt = 0; mt < 2; mt++) {
                    mma8(acc[mt][nt], a[mt][0], a[mt][1], a[mt][2], a[mt][3], b0, b1);
                }
            }
        }
        __syncthreads();
    }

    // epilogue: accumulate into out
    #pragma unroll
    for (int mt = 0; mt < 2; mt++) {
        int r0 = tok0 + bm + wm + mt * 16 + g;
        int r1 = r0 + 8;
        #pragma unroll
        for (int nt = 0; nt < 4; nt++) {
            int c = bn + wn + nt * 8 + 2 * tig;
            float2* p0 = (float2*)&out[(size_t)r0 * DIM + c];
            float2* p1 = (float2*)&out[(size_t)r1 * DIM + c];
            float2 v0 = make_float2(acc[mt][nt][0], acc[mt][nt][1]);
            float2 v1 = make_float2(acc[mt][nt][2], acc[mt][nt][3]);
            if (!first) {
                float2 o0 = *p0; v0.x += o0.x; v0.y += o0.y;
                float2 o1 = *p1; v1.x += o1.x; v1.y += o1.y;
            }
            *p0 = v0;
            *p1 = v1;
        }
    }
}

// ---------------------------------------------------------------------------
extern "C" void kernel_launch(void* const* d_in, const int* in_sizes, int n_in,
                              void* d_out, int out_size) {
    const float* x   = (const float*)d_in[0];  // [2,2048,1024]
    const float* gw  = (const float*)d_in[1];  // [8,1024]
    const float* w1  = (const float*)d_in[2];  // [8,1024,5632]
    const float* w2  = (const float*)d_in[3];  // [8,5632,1024]
    const float* w3  = (const float*)d_in[4];  // [8,1024,5632]
    float* out = (float*)d_out;                // [2,2048,1024]

    gate_kernel<<<T_TOK / 4, 128>>>(x, gw);

    for (int e = 0; e < EACT; e++) {
        const float* w1e = w1 + (size_t)e * DIM * HID;
        const float* w3e = w3 + (size_t)e * DIM * HID;
        const float* w2e = w2 + (size_t)e * HID * DIM;
        for (int tb = 0; tb < T_TOK / TB; tb++) {
            int tok0 = tb * TB;
            gemm13_kernel<<<dim3(HID / 64, TB / 128), 256>>>(x, w1e, w3e, e, tok0);
            gemm2_kernel<<<dim3(DIM / 64, TB / 128), 256>>>(w2e, out, e == 0, tok0);
        }
    }
}

// round 5
// speedup vs baseline: 2.5253x; 2.5253x over previous
#include <cuda_runtime.h>
#include <cstdint>

// Problem constants
#define T_TOK 4096
#define DIM   1024
#define HID   5632
#define EACT  4
#define TB    1024   // token tile for scratch reuse

// Scratch: combine weights + intermediate G (tf32 bits), one token-block (23 MB)
__device__ float g_cw[T_TOK * EACT];
__device__ __align__(16) uint32_t g_G[(size_t)TB * HID];

__device__ __forceinline__ uint32_t f2tf32(float f) {
    uint32_t r;
    asm("cvt.rna.tf32.f32 %0, %1;" : "=r"(r) : "f"(f));
    return r;
}
__device__ __forceinline__ uint32_t b2tf32(uint32_t b) {
    return f2tf32(__uint_as_float(b));
}

__device__ __forceinline__ void cp16(uint32_t* smem_ptr, const void* gptr) {
    uint32_t a = (uint32_t)__cvta_generic_to_shared(smem_ptr);
    asm volatile("cp.async.cg.shared.global [%0], [%1], 16;" :: "r"(a), "l"(gptr));
}
#define CP_COMMIT() asm volatile("cp.async.commit_group;")
#define CP_WAIT0()  asm volatile("cp.async.wait_group 0;")

__device__ __forceinline__ void mma8(float* c,
                                     uint32_t a0, uint32_t a1, uint32_t a2, uint32_t a3,
                                     uint32_t b0, uint32_t b1) {
    asm volatile(
        "mma.sync.aligned.m16n8k8.row.col.f32.tf32.tf32.f32 "
        "{%0,%1,%2,%3}, {%4,%5,%6,%7}, {%8,%9}, {%0,%1,%2,%3};\n"
        : "+f"(c[0]), "+f"(c[1]), "+f"(c[2]), "+f"(c[3])
        : "r"(a0), "r"(a1), "r"(a2), "r"(a3), "r"(b0), "r"(b1));
}

__device__ __forceinline__ float silu_f(float v) {
    return v / (1.0f + __expf(-v));
}

// ---------------------------------------------------------------------------
// Gate: one warp per token; experts 4..7 masked. softmax->top2->renorm ==
// softmax over the two best logits.
// ---------------------------------------------------------------------------
__global__ void gate_kernel(const float* __restrict__ x,
                            const float* __restrict__ gw) {
    int warp = (blockIdx.x * blockDim.x + threadIdx.x) >> 5;
    int lane = threadIdx.x & 31;
    if (warp >= T_TOK) return;

    const float* xr = x + (size_t)warp * DIM;
    float p0 = 0.f, p1 = 0.f, p2 = 0.f, p3 = 0.f;
    for (int d = lane; d < DIM; d += 32) {
        float xv = xr[d];
        p0 += xv * gw[0 * DIM + d];
        p1 += xv * gw[1 * DIM + d];
        p2 += xv * gw[2 * DIM + d];
        p3 += xv * gw[3 * DIM + d];
    }
    #pragma unroll
    for (int off = 16; off; off >>= 1) {
        p0 += __shfl_down_sync(0xffffffff, p0, off);
        p1 += __shfl_down_sync(0xffffffff, p1, off);
        p2 += __shfl_down_sync(0xffffffff, p2, off);
        p3 += __shfl_down_sync(0xffffffff, p3, off);
    }
    if (lane == 0) {
        float l[4] = {p0, p1, p2, p3};
        int i0 = 0;
        #pragma unroll
        for (int e = 1; e < 4; e++) if (l[e] > l[i0]) i0 = e;
        int i1 = -1;
        #pragma unroll
        for (int e = 0; e < 4; e++) {
            if (e == i0) continue;
            if (i1 < 0 || l[e] > l[i1]) i1 = e;
        }
        float w0 = 1.0f / (1.0f + __expf(l[i1] - l[i0]));
        float w1 = 1.0f - w0;
        float* cwr = g_cw + warp * 4;
        cwr[0] = 0.f; cwr[1] = 0.f; cwr[2] = 0.f; cwr[3] = 0.f;
        cwr[i0] = w0;
        cwr[i1] = w1;
    }
}

// ---------------------------------------------------------------------------
// GEMM13: G[t,h] = tf32( cw[t,e] * silu(X@W1)[t,h] * (X@W3)[t,h] )
// BM=128, BN=64, BK=32; 2-stage cp.async; XOR-swizzled smem (conflict-free).
// Dynamic smem: 2 stages x (A 16KB + B1 8KB + B3 8KB) = 64KB.
// ---------------------------------------------------------------------------
#define G13_STAGE_WORDS 8192

__device__ __forceinline__ void g13_load_stage(
    uint32_t* sm, int s, int k0,
    const float* X, const float* W1, const float* W3,
    int tid, int bm, int bn, int tok0)
{
    uint32_t* A  = sm + s * G13_STAGE_WORDS;
    uint32_t* B1 = A + 4096;
    uint32_t* B3 = A + 6144;
    #pragma unroll
    for (int i = 0; i < 4; i++) {
        int id  = tid + i * 256;
        int row = id >> 3;
        int c4  = (id & 7) * 4;
        cp16(A + row * 32 + (c4 ^ ((row & 7) * 4)),
             X + (size_t)(tok0 + bm + row) * DIM + k0 + c4);
    }
    #pragma unroll
    for (int i = 0; i < 2; i++) {
        int id  = tid + i * 256;
        int row = id >> 4;
        int c4  = (id & 15) * 4;
        int pc  = c4 ^ ((row & 3) * 8);
        size_t goff = (size_t)(k0 + row) * HID + bn + c4;
        cp16(B1 + row * 64 + pc, W1 + goff);
        cp16(B3 + row * 64 + pc, W3 + goff);
    }
    CP_COMMIT();
}

__global__ void __launch_bounds__(256, 2) gemm13_kernel(
    const float* __restrict__ X,
    const float* __restrict__ W1,
    const float* __restrict__ W3,
    int eidx, int tok0)
{
    extern __shared__ __align__(16) uint32_t sm[];

    const int tid  = threadIdx.x;
    const int bm   = blockIdx.y * 128;
    const int bn   = blockIdx.x * 64;
    const int warp = tid >> 5;
    const int lane = tid & 31;
    const int wm   = (warp & 3) * 32;
    const int wn   = (warp >> 2) * 32;
    const int g    = lane >> 2;
    const int tig  = lane & 3;

    float accA[2][4][4];
    float accB[2][4][4];
    #pragma unroll
    for (int mt = 0; mt < 2; mt++)
        #pragma unroll
        for (int nt = 0; nt < 4; nt++)
            #pragma unroll
            for (int i = 0; i < 4; i++) { accA[mt][nt][i] = 0.f; accB[mt][nt][i] = 0.f; }

    g13_load_stage(sm, 0, 0, X, W1, W3, tid, bm, bn, tok0);

    for (int it = 0; it < DIM / 32; it++) {
        CP_WAIT0();
        __syncthreads();
        int s = it & 1;
        if (it + 1 < DIM / 32)
            g13_load_stage(sm, s ^ 1, (it + 1) * 32, X, W1, W3, tid, bm, bn, tok0);

        const uint32_t* A  = sm + s * G13_STAGE_WORDS;
        const uint32_t* B1 = A + 4096;
        const uint32_t* B3 = A + 6144;

        #pragma unroll
        for (int kk = 0; kk < 32; kk += 8) {
            uint32_t a[2][4];
            const int xo = 4 * g;             // (row&7) == g for all fragment rows
            #pragma unroll
            for (int mt = 0; mt < 2; mt++) {
                int r = wm + mt * 16 + g;
                a[mt][0] = b2tf32(A[(size_t)r * 32 + ((kk + tig) ^ xo)]);
                a[mt][1] = b2tf32(A[(size_t)(r + 8) * 32 + ((kk + tig) ^ xo)]);
                a[mt][2] = b2tf32(A[(size_t)r * 32 + ((kk + tig + 4) ^ xo)]);
                a[mt][3] = b2tf32(A[(size_t)(r + 8) * 32 + ((kk + tig + 4) ^ xo)]);
            }
            const int krow = kk + tig;
            const int ko   = (krow & 3) * 8;  // same for krow and krow+4
            #pragma unroll
            for (int nt = 0; nt < 4; nt++) {
                int n  = wn + nt * 8 + g;
                int pc = n ^ ko;
                uint32_t b1a = b2tf32(B1[krow * 64 + pc]);
                uint32_t b1b = b2tf32(B1[(krow + 4) * 64 + pc]);
                uint32_t b3a = b2tf32(B3[krow * 64 + pc]);
                uint32_t b3b = b2tf32(B3[(krow + 4) * 64 + pc]);
                #pragma unroll
                for (int mt = 0; mt < 2; mt++) {
                    mma8(accA[mt][nt], a[mt][0], a[mt][1], a[mt][2], a[mt][3], b1a, b1b);
                    mma8(accB[mt][nt], a[mt][0], a[mt][1], a[mt][2], a[mt][3], b3a, b3b);
                }
            }
        }
    }

    // epilogue: G = tf32(cw * silu(A) * B)
    #pragma unroll
    for (int mt = 0; mt < 2; mt++) {
        int r0 = bm + wm + mt * 16 + g;
        int r1 = r0 + 8;
        float cw0 = g_cw[(tok0 + r0) * 4 + eidx];
        float cw1 = g_cw[(tok0 + r1) * 4 + eidx];
        #pragma unroll
        for (int nt = 0; nt < 4; nt++) {
            int c = bn + wn + nt * 8 + 2 * tig;
            float v00 = silu_f(accA[mt][nt][0]) * accB[mt][nt][0] * cw0;
            float v01 = silu_f(accA[mt][nt][1]) * accB[mt][nt][1] * cw0;
            float v10 = silu_f(accA[mt][nt][2]) * accB[mt][nt][2] * cw1;
            float v11 = silu_f(accA[mt][nt][3]) * accB[mt][nt][3] * cw1;
            uint2 s0 = make_uint2(f2tf32(v00), f2tf32(v01));
            uint2 s1 = make_uint2(f2tf32(v10), f2tf32(v11));
            *(uint2*)&g_G[(size_t)r0 * HID + c] = s0;
            *(uint2*)&g_G[(size_t)r1 * HID + c] = s1;
        }
    }
}

// ---------------------------------------------------------------------------
// GEMM2: out[tok0+t,d] (+)= (G @ W2)[t,d]
// BM=64, BN=64, BK=32; 2-stage cp.async; swizzled smem. Static 32KB smem.
// Grid 16x16 = 256 CTAs.
// ---------------------------------------------------------------------------
#define G2_STAGE_WORDS 4096

__device__ __forceinline__ void g2_load_stage(
    uint32_t* sm, int s, int k0,
    const float* W2, int tid, int bm, int bn)
{
    uint32_t* A = sm + s * G2_STAGE_WORDS;
    uint32_t* B = A + 2048;
    #pragma unroll
    for (int i = 0; i < 2; i++) {
        int id  = tid + i * 256;
        int row = id >> 3;
        int c4  = (id & 7) * 4;
        cp16(A + row * 32 + (c4 ^ ((row & 7) * 4)),
             g_G + (size_t)(bm + row) * HID + k0 + c4);
    }
    #pragma unroll
    for (int i = 0; i < 2; i++) {
        int id  = tid + i * 256;
        int row = id >> 4;
        int c4  = (id & 15) * 4;
        cp16(B + row * 64 + (c4 ^ ((row & 3) * 8)),
             W2 + (size_t)(k0 + row) * DIM + bn + c4);
    }
    CP_COMMIT();
}

__global__ void __launch_bounds__(256) gemm2_kernel(
    const float* __restrict__ W2,
    float* __restrict__ out,
    int first, int tok0)
{
    __shared__ __align__(16) uint32_t sm[2 * G2_STAGE_WORDS];

    const int tid  = threadIdx.x;
    const int bm   = blockIdx.y * 64;
    const int bn   = blockIdx.x * 64;
    const int warp = tid >> 5;
    const int lane = tid & 31;
    const int wm   = (warp & 1) * 32;
    const int wn   = (warp >> 1) * 16;
    const int g    = lane >> 2;
    const int tig  = lane & 3;

    float acc[2][2][4];
    #pragma unroll
    for (int mt = 0; mt < 2; mt++)
        #pragma unroll
        for (int nt = 0; nt < 2; nt++)
            #pragma unroll
            for (int i = 0; i < 4; i++) acc[mt][nt][i] = 0.f;

    g2_load_stage(sm, 0, 0, W2, tid, bm, bn);

    for (int it = 0; it < HID / 32; it++) {
        CP_WAIT0();
        __syncthreads();
        int s = it & 1;
        if (it + 1 < HID / 32)
            g2_load_stage(sm, s ^ 1, (it + 1) * 32, W2, tid, bm, bn);

        const uint32_t* A = sm + s * G2_STAGE_WORDS;
        const uint32_t* B = A + 2048;

        #pragma unroll
        for (int kk = 0; kk < 32; kk += 8) {
            uint32_t a[2][4];
            const int xo = 4 * g;
            #pragma unroll
            for (int mt = 0; mt < 2; mt++) {
                int r = wm + mt * 16 + g;
                a[mt][0] = A[(size_t)r * 32 + ((kk + tig) ^ xo)];
                a[mt][1] = A[(size_t)(r + 8) * 32 + ((kk + tig) ^ xo)];
                a[mt][2] = A[(size_t)r * 32 + ((kk + tig + 4) ^ xo)];
                a[mt][3] = A[(size_t)(r + 8) * 32 + ((kk + tig + 4) ^ xo)];
            }
            const int krow = kk + tig;
            const int ko   = (krow & 3) * 8;
            #pragma unroll
            for (int nt = 0; nt < 2; nt++) {
                int n  = wn + nt * 8 + g;
                int pc = n ^ ko;
                uint32_t b0 = b2tf32(B[krow * 64 + pc]);
                uint32_t b1 = b2tf32(B[(krow + 4) * 64 + pc]);
                #pragma unroll
                for (int mt = 0; mt < 2; mt++)
                    mma8(acc[mt][nt], a[mt][0], a[mt][1], a[mt][2], a[mt][3], b0, b1);
            }
        }
    }

    // epilogue: accumulate into out
    #pragma unroll
    for (int mt = 0; mt < 2; mt++) {
        int r0 = tok0 + bm + wm + mt * 16 + g;
        int r1 = r0 + 8;
        #pragma unroll
        for (int nt = 0; nt < 2; nt++) {
            int c = bn + wn + nt * 8 + 2 * tig;
            float2* p0 = (float2*)&out[(size_t)r0 * DIM + c];
            float2* p1 = (float2*)&out[(size_t)r1 * DIM + c];
            float2 v0 = make_float2(acc[mt][nt][0], acc[mt][nt][1]);
            float2 v1 = make_float2(acc[mt][nt][2], acc[mt][nt][3]);
            if (!first) {
                float2 o0 = *p0; v0.x += o0.x; v0.y += o0.y;
                float2 o1 = *p1; v1.x += o1.x; v1.y += o1.y;
            }
            *p0 = v0;
            *p1 = v1;
        }
    }
}

// ---------------------------------------------------------------------------
extern "C" void kernel_launch(void* const* d_in, const int* in_sizes, int n_in,
                              void* d_out, int out_size) {
    const float* x   = (const float*)d_in[0];  // [2,2048,1024]
    const float* gw  = (const float*)d_in[1];  // [8,1024]
    const float* w1  = (const float*)d_in[2];  // [8,1024,5632]
    const float* w2  = (const float*)d_in[3];  // [8,5632,1024]
    const float* w3  = (const float*)d_in[4];  // [8,1024,5632]
    float* out = (float*)d_out;                // [2,2048,1024]

    cudaFuncSetAttribute(gemm13_kernel,
                         cudaFuncAttributeMaxDynamicSharedMemorySize, 65536);

    gate_kernel<<<T_TOK / 4, 128>>>(x, gw);

    for (int e = 0; e < EACT; e++) {
        const float* w1e = w1 + (size_t)e * DIM * HID;
        const float* w3e = w3 + (size_t)e * DIM * HID;
        const float* w2e = w2 + (size_t)e * HID * DIM;
        for (int tb = 0; tb < T_TOK / TB; tb++) {
            int tok0 = tb * TB;
            gemm13_kernel<<<dim3(HID / 64, TB / 128), 256, 65536>>>(x, w1e, w3e, e, tok0);
            gemm2_kernel<<<dim3(DIM / 64, TB / 64), 256>>>(w2e, out, e == 0, tok0);
        }
    }
}